// round 1
// baseline (speedup 1.0000x reference)
#include <cuda_runtime.h>

#define GNUM   2048
#define NPG    57
#define NNODES (GNUM*NPG)      // 116736
#define EPG    160
#define NEDGES (GNUM*EPG)      // 327680
#define HID    256
#define NLAY   5
#define NEF    (GNUM*80)       // 163840

// ---------------- scratch (static __device__ arrays; no allocs) ----------------
__device__ float d_h   [(size_t)NNODES*HID];   // node features
__device__ float d_t2  [(size_t)NNODES*HID];   // update hidden
__device__ float d_agg [(size_t)NNODES*HID];   // scatter accumulator
__device__ float d_t1  [(size_t)NEDGES*HID];   // message hidden
__device__ float d_t3  [(size_t)NEF  *HID];    // readout hidden
__device__ float d_invdeg [NNODES];
__device__ float d_bnscale[NLAY*HID];
__device__ float d_bnshift[NLAY*HID];

// ---------------- small helper kernels ----------------
__global__ void zero_agg_kernel() {
    size_t n4 = (size_t)NNODES*HID/4;
    float4 z = make_float4(0.f,0.f,0.f,0.f);
    for (size_t i = (size_t)blockIdx.x*blockDim.x + threadIdx.x; i < n4;
         i += (size_t)gridDim.x*blockDim.x)
        ((float4*)d_agg)[i] = z;
}

__global__ void deg_zero_kernel() {
    int i = blockIdx.x*blockDim.x + threadIdx.x;
    if (i < NNODES) d_invdeg[i] = 0.f;
}
__global__ void deg_count_kernel(const int* __restrict__ dst) {
    int e = blockIdx.x*blockDim.x + threadIdx.x;
    if (e < NEDGES) atomicAdd(&d_invdeg[dst[e]], 1.f);
}
__global__ void deg_inv_kernel() {
    int i = blockIdx.x*blockDim.x + threadIdx.x;
    if (i < NNODES) d_invdeg[i] = 1.f / fmaxf(d_invdeg[i], 1.f);
}

__global__ void bn_prep_kernel(const float* __restrict__ g, const float* __restrict__ b,
                               const float* __restrict__ m, const float* __restrict__ v) {
    int i = blockIdx.x*blockDim.x + threadIdx.x;
    if (i < NLAY*HID) {
        float sc = g[i] * rsqrtf(v[i] + 1e-5f);
        d_bnscale[i] = sc;
        d_bnshift[i] = b[i] - m[i]*sc;
    }
}

// h = x @ in_w + in_b   ([N,16] @ [16,256])
__global__ void input_gemm_kernel(const float* __restrict__ x,
                                  const float* __restrict__ w,
                                  const float* __restrict__ b) {
    int n = blockIdx.x;
    int c = threadIdx.x;
    __shared__ float xs[16];
    if (c < 16) xs[c] = x[n*16 + c];
    __syncthreads();
    float acc = b[c];
#pragma unroll
    for (int k = 0; k < 16; k++) acc = fmaf(xs[k], w[k*HID + c], acc);
    d_h[(size_t)n*HID + c] = acc;
}

// ---------------- fused tiled SGEMM: [M,K] @ [K,256] ----------------
// BM=64, BN=256(full), BK=16, 256 threads, 8x8 micro-tile.
// AMODE: 0 = A=d_t1 (K=256)            | 1 = A=d_t2 (K=256)
//        2 = A=concat(h[dst], h[src])  | 3 = A=concat(h, agg*invdeg)
//        4 = A=concat(h[u_idx], h[v_idx]) (branch tables computed inline)
// EPI:   0 = relu(acc+bias) -> out(t1/t2/t3 by AMODE)
//        1 = acc+bias -> atomicAdd into d_agg[dst[row]]
//        2 = acc+bias -> BN -> relu -> += d_h (residual) -> d_h
template<int AMODE, int EPI>
__global__ __launch_bounds__(256, 2)
void gemm256(const float* __restrict__ W, const float* __restrict__ bias,
             const int* __restrict__ srcI, const int* __restrict__ dstI,
             int K, int layer)
{
    __shared__ float As[16][68];    // [k][m], padded
    __shared__ float Ws[16][256];   // [k][n]

    const int tid  = threadIdx.x;
    const int row0 = blockIdx.x * 64;
    const int lrow = tid >> 2;          // 0..63: A-load row
    const int kq4  = (tid & 3) * 4;     // A-load k offset
    const int r    = row0 + lrow;

    const float* abase0;
    const float* abase1 = nullptr;
    float ascale = 1.f;
    if constexpr (AMODE == 0) {
        abase0 = d_t1 + (size_t)r*HID;
    } else if constexpr (AMODE == 1) {
        abase0 = d_t2 + (size_t)r*HID;
    } else if constexpr (AMODE == 2) {
        abase0 = d_h + (size_t)dstI[r]*HID;
        abase1 = d_h + (size_t)srcI[r]*HID;
    } else if constexpr (AMODE == 3) {
        abase0 = d_h   + (size_t)r*HID;
        abase1 = d_agg + (size_t)r*HID;
        ascale = d_invdeg[r];
    } else {
        int g = r / 80, b = r % 80;
        int u = g*NPG + (b % 57);
        int v = g*NPG + ((b*13 + 1) % 57);
        abase0 = d_h + (size_t)u*HID;
        abase1 = d_h + (size_t)v*HID;
    }

    const int wk = tid >> 6;            // 0..3  W-load k base
    const int wn = (tid & 63) * 4;      // W-load col
    const int tx = tid & 31;            // micro-tile col group (cols tx*8..)
    const int ty = tid >> 5;            // micro-tile row group (rows ty*8..)

    float acc[8][8];
#pragma unroll
    for (int i = 0; i < 8; i++)
#pragma unroll
        for (int j = 0; j < 8; j++) acc[i][j] = 0.f;

    const int nsteps = K >> 4;
    for (int t = 0; t < nsteps; t++) {
        const int k0 = t << 4;
        // fetch A fragment (gathered / concatenated)
        const int kk = k0 + kq4;
        float4 av;
        if (kk < 256) {
            av = *(const float4*)(abase0 + kk);
        } else {
            av = *(const float4*)(abase1 + (kk - 256));
            if constexpr (AMODE == 3) {
                av.x *= ascale; av.y *= ascale; av.z *= ascale; av.w *= ascale;
            }
        }
        // fetch W fragments
        float4 wv[4];
#pragma unroll
        for (int i = 0; i < 4; i++)
            wv[i] = *(const float4*)(W + (size_t)(k0 + wk + i*4)*HID + wn);

        __syncthreads();
        As[kq4+0][lrow] = av.x;
        As[kq4+1][lrow] = av.y;
        As[kq4+2][lrow] = av.z;
        As[kq4+3][lrow] = av.w;
#pragma unroll
        for (int i = 0; i < 4; i++)
            *(float4*)&Ws[wk + i*4][wn] = wv[i];
        __syncthreads();

#pragma unroll
        for (int k = 0; k < 16; k++) {
            float4 a0 = *(const float4*)&As[k][ty*8];
            float4 a1 = *(const float4*)&As[k][ty*8 + 4];
            float4 b0 = *(const float4*)&Ws[k][tx*8];
            float4 b1 = *(const float4*)&Ws[k][tx*8 + 4];
            float av8[8] = {a0.x,a0.y,a0.z,a0.w,a1.x,a1.y,a1.z,a1.w};
            float bv8[8] = {b0.x,b0.y,b0.z,b0.w,b1.x,b1.y,b1.z,b1.w};
#pragma unroll
            for (int i = 0; i < 8; i++)
#pragma unroll
                for (int j = 0; j < 8; j++)
                    acc[i][j] = fmaf(av8[i], bv8[j], acc[i][j]);
        }
    }

    // bias for this thread's 8 columns
    float4 bb0 = *(const float4*)(bias + tx*8);
    float4 bb1 = *(const float4*)(bias + tx*8 + 4);
    float bs[8] = {bb0.x,bb0.y,bb0.z,bb0.w,bb1.x,bb1.y,bb1.z,bb1.w};

    if constexpr (EPI == 0) {
        float* out = (AMODE == 2) ? d_t1 : (AMODE == 3 ? d_t2 : d_t3);
#pragma unroll
        for (int i = 0; i < 8; i++) {
            int rr = row0 + ty*8 + i;
            float o[8];
#pragma unroll
            for (int j = 0; j < 8; j++) o[j] = fmaxf(acc[i][j] + bs[j], 0.f);
            *(float4*)(out + (size_t)rr*HID + tx*8)     = make_float4(o[0],o[1],o[2],o[3]);
            *(float4*)(out + (size_t)rr*HID + tx*8 + 4) = make_float4(o[4],o[5],o[6],o[7]);
        }
    } else if constexpr (EPI == 1) {
#pragma unroll
        for (int i = 0; i < 8; i++) {
            int rr = row0 + ty*8 + i;
            int node = dstI[rr];
            float* ag = d_agg + (size_t)node*HID + tx*8;
#pragma unroll
            for (int j = 0; j < 8; j++)
                atomicAdd(ag + j, acc[i][j] + bs[j]);
        }
    } else { // EPI == 2: BN + relu + residual -> d_h
        const float* scp = d_bnscale + layer*HID;
        const float* shp = d_bnshift + layer*HID;
        float4 s0 = *(const float4*)(scp + tx*8);
        float4 s1 = *(const float4*)(scp + tx*8 + 4);
        float4 h0 = *(const float4*)(shp + tx*8);
        float4 h1 = *(const float4*)(shp + tx*8 + 4);
        float sc[8] = {s0.x,s0.y,s0.z,s0.w,s1.x,s1.y,s1.z,s1.w};
        float sh[8] = {h0.x,h0.y,h0.z,h0.w,h1.x,h1.y,h1.z,h1.w};
#pragma unroll
        for (int i = 0; i < 8; i++) {
            int rr = row0 + ty*8 + i;
            float* hp = d_h + (size_t)rr*HID + tx*8;
            float4 r0 = *(const float4*)hp;
            float4 r1 = *(const float4*)(hp + 4);
            float res[8] = {r0.x,r0.y,r0.z,r0.w,r1.x,r1.y,r1.z,r1.w};
            float o[8];
#pragma unroll
            for (int j = 0; j < 8; j++) {
                float u = acc[i][j] + bs[j];
                u = fmaf(u, sc[j], sh[j]);
                o[j] = fmaxf(u, 0.f) + res[j];
            }
            *(float4*)hp       = make_float4(o[0],o[1],o[2],o[3]);
            *(float4*)(hp + 4) = make_float4(o[4],o[5],o[6],o[7]);
        }
    }
}

// out[row] = relu-free dot: t3[row,:] @ mlp_w2[:,0] + mlp_b2
__global__ void final_dot_kernel(const float* __restrict__ w2,
                                 const float* __restrict__ b2,
                                 float* __restrict__ out) {
    int row  = blockIdx.x*8 + (threadIdx.x >> 5);
    int lane = threadIdx.x & 31;
    const float* t = d_t3 + (size_t)row*HID;
    float s = 0.f;
#pragma unroll
    for (int k = lane; k < HID; k += 32) s = fmaf(t[k], w2[k], s);
#pragma unroll
    for (int o = 16; o > 0; o >>= 1) s += __shfl_down_sync(0xffffffffu, s, o);
    if (lane == 0) out[row] = s + b2[0];
}

// ---------------- launch ----------------
extern "C" void kernel_launch(void* const* d_in, const int* in_sizes, int n_in,
                              void* d_out, int out_size)
{
    const float* x      = (const float*)d_in[0];
    const int*   ei     = (const int*)  d_in[1];
    // d_in[2] = num_graphs (compile-time constant here)
    const float* in_w   = (const float*)d_in[3];
    const float* in_b   = (const float*)d_in[4];
    const float* msg_w1 = (const float*)d_in[5];
    const float* msg_b1 = (const float*)d_in[6];
    const float* msg_w2 = (const float*)d_in[7];
    const float* msg_b2 = (const float*)d_in[8];
    const float* upd_w1 = (const float*)d_in[9];
    const float* upd_b1 = (const float*)d_in[10];
    const float* upd_w2 = (const float*)d_in[11];
    const float* upd_b2 = (const float*)d_in[12];
    const float* bn_g   = (const float*)d_in[13];
    const float* bn_b   = (const float*)d_in[14];
    const float* bn_m   = (const float*)d_in[15];
    const float* bn_v   = (const float*)d_in[16];
    const float* mlp_w1 = (const float*)d_in[17];
    const float* mlp_b1 = (const float*)d_in[18];
    const float* mlp_w2 = (const float*)d_in[19];
    const float* mlp_b2 = (const float*)d_in[20];
    float* out = (float*)d_out;

    const int* srcI = ei;            // edge_index[0] = src (x_j)
    const int* dstI = ei + NEDGES;   // edge_index[1] = dst (x_i, aggregation target)

    deg_zero_kernel <<<(NNODES+255)/256, 256>>>();
    deg_count_kernel<<<(NEDGES+255)/256, 256>>>(dstI);
    deg_inv_kernel  <<<(NNODES+255)/256, 256>>>();
    bn_prep_kernel  <<<(NLAY*HID+255)/256, 256>>>(bn_g, bn_b, bn_m, bn_v);
    input_gemm_kernel<<<NNODES, 256>>>(x, in_w, in_b);

    for (int l = 0; l < NLAY; l++) {
        zero_agg_kernel<<<2048, 256>>>();
        // message MLP: relu(cat[h[dst],h[src]] @ W1 + b1) -> t1
        gemm256<2,0><<<NEDGES/64, 256>>>(msg_w1 + (size_t)l*512*HID, msg_b1 + l*HID,
                                         srcI, dstI, 512, l);
        // t1 @ W2 + b2 -> atomic scatter into agg[dst]
        gemm256<0,1><<<NEDGES/64, 256>>>(msg_w2 + (size_t)l*HID*HID, msg_b2 + l*HID,
                                         srcI, dstI, 256, l);
        // update MLP: relu(cat[h, agg*invdeg] @ W1 + b1) -> t2
        gemm256<3,0><<<NNODES/64, 256>>>(upd_w1 + (size_t)l*512*HID, upd_b1 + l*HID,
                                         srcI, dstI, 512, l);
        // t2 @ W2 + b2 -> BN -> relu -> + residual -> h
        gemm256<1,2><<<NNODES/64, 256>>>(upd_w2 + (size_t)l*HID*HID, upd_b2 + l*HID,
                                         srcI, dstI, 256, l);
    }

    // readout: relu(cat[h[u],h[v]] @ mlp_w1 + b1) -> t3 ; t3 @ mlp_w2 + b2 -> out
    gemm256<4,0><<<NEF/64, 256>>>(mlp_w1, mlp_b1, nullptr, nullptr, 512, 0);
    final_dot_kernel<<<NEF/8, 256>>>(mlp_w2, mlp_b2, out);
}

// round 6
// speedup vs baseline: 2.2852x; 2.2852x over previous
#include <cuda_runtime.h>
#include <cuda_bf16.h>
#include <cstdint>

#define GNUM   2048
#define NPG    57
#define NNODES (GNUM*NPG)      // 116736
#define EPG    160
#define NEDGES (GNUM*EPG)      // 327680
#define HID    256
#define NLAY   5
#define NEF    (GNUM*80)       // 163840

// ---------------- scratch (static __device__ arrays; no allocs) ----------------
__device__ float d_h   [(size_t)NNODES*HID];
__device__ float d_t2  [(size_t)NNODES*HID];
__device__ float d_agg [(size_t)NNODES*HID];
__device__ float d_t1  [(size_t)NEDGES*HID];
__device__ float d_t3  [(size_t)NEF  *HID];
__device__ float d_invdeg [NNODES];
__device__ float d_bnscale[NLAY*HID];
__device__ float d_bnshift[NLAY*HID];
// transposed, bf16-split weights: [256 out, K] K-major, hi + lo parts
__device__ unsigned short d_bhi_m1[(size_t)NLAY*256*512];
__device__ unsigned short d_blo_m1[(size_t)NLAY*256*512];
__device__ unsigned short d_bhi_m2[(size_t)NLAY*256*256];
__device__ unsigned short d_blo_m2[(size_t)NLAY*256*256];
__device__ unsigned short d_bhi_u1[(size_t)NLAY*256*512];
__device__ unsigned short d_blo_u1[(size_t)NLAY*256*512];
__device__ unsigned short d_bhi_u2[(size_t)NLAY*256*256];
__device__ unsigned short d_blo_u2[(size_t)NLAY*256*256];
__device__ unsigned short d_bhi_r [(size_t)256*512];
__device__ unsigned short d_blo_r [(size_t)256*512];

// ---------------- PTX helpers (family-target-safe: sm_80 base features) ----
__device__ __forceinline__ uint32_t smem_u32(const void* p) {
    uint32_t a;
    asm("{ .reg .u64 t; cvta.to.shared.u64 t, %1; cvt.u32.u64 %0, t; }" : "=r"(a) : "l"(p));
    return a;
}
__device__ __forceinline__ void cp_async16(uint32_t smem, const void* g) {
    asm volatile("cp.async.cg.shared.global [%0], [%1], 16;" :: "r"(smem), "l"(g) : "memory");
}
#define CP_COMMIT() asm volatile("cp.async.commit_group;" ::: "memory")
#define CP_WAIT1()  asm volatile("cp.async.wait_group 1;" ::: "memory")
#define CP_WAIT0()  asm volatile("cp.async.wait_group 0;" ::: "memory")

// D += A*B  (m16n8k16 bf16, f32 accum)
__device__ __forceinline__ void mma_bf16(float* d, const uint32_t* a, const uint32_t* b) {
    asm volatile(
        "mma.sync.aligned.m16n8k16.row.col.f32.bf16.bf16.f32 "
        "{%0,%1,%2,%3}, {%4,%5,%6,%7}, {%8,%9}, {%0,%1,%2,%3};"
        : "+f"(d[0]), "+f"(d[1]), "+f"(d[2]), "+f"(d[3])
        : "r"(a[0]), "r"(a[1]), "r"(a[2]), "r"(a[3]), "r"(b[0]), "r"(b[1]));
}
__device__ __forceinline__ void red_add_v2(float* p, float a, float b) {
    asm volatile("red.global.add.v2.f32 [%0], {%1, %2};"
                 :: "l"(p), "f"(a), "f"(b) : "memory");
}
// split float2 -> packed bf16x2 hi + lo (lo = value minus hi, re-rounded)
__device__ __forceinline__ void split_bf16x2(float2 v, uint32_t& hi, uint32_t& lo) {
    asm("cvt.rn.bf16x2.f32 %0, %1, %2;" : "=r"(hi) : "f"(v.y), "f"(v.x));
    float hlo = __uint_as_float(hi << 16);
    float hhi = __uint_as_float(hi & 0xFFFF0000u);
    asm("cvt.rn.bf16x2.f32 %0, %1, %2;" : "=r"(lo) : "f"(v.y - hhi), "f"(v.x - hlo));
}

// ---------------- small helper kernels ----------------
__global__ void zero_agg_kernel() {
    size_t n4 = (size_t)NNODES*HID/4;
    float4 z = make_float4(0.f,0.f,0.f,0.f);
    for (size_t i = (size_t)blockIdx.x*blockDim.x + threadIdx.x; i < n4;
         i += (size_t)gridDim.x*blockDim.x)
        ((float4*)d_agg)[i] = z;
}
__global__ void scale_agg_kernel() {
    size_t n4 = (size_t)NNODES*HID/4;
    for (size_t i = (size_t)blockIdx.x*blockDim.x + threadIdx.x; i < n4;
         i += (size_t)gridDim.x*blockDim.x) {
        int row = (int)(i >> 6);
        float s = d_invdeg[row];
        float4 v = ((float4*)d_agg)[i];
        v.x*=s; v.y*=s; v.z*=s; v.w*=s;
        ((float4*)d_agg)[i] = v;
    }
}
__global__ void deg_zero_kernel() {
    int i = blockIdx.x*blockDim.x + threadIdx.x;
    if (i < NNODES) d_invdeg[i] = 0.f;
}
__global__ void deg_count_kernel(const int* __restrict__ dst) {
    int e = blockIdx.x*blockDim.x + threadIdx.x;
    if (e < NEDGES) atomicAdd(&d_invdeg[dst[e]], 1.f);
}
__global__ void deg_inv_kernel() {
    int i = blockIdx.x*blockDim.x + threadIdx.x;
    if (i < NNODES) d_invdeg[i] = 1.f / fmaxf(d_invdeg[i], 1.f);
}
__global__ void bn_prep_kernel(const float* __restrict__ g, const float* __restrict__ b,
                               const float* __restrict__ m, const float* __restrict__ v) {
    int i = blockIdx.x*blockDim.x + threadIdx.x;
    if (i < NLAY*HID) {
        float sc = g[i] * rsqrtf(v[i] + 1e-5f);
        d_bnscale[i] = sc;
        d_bnshift[i] = b[i] - m[i]*sc;
    }
}
__global__ void input_gemm_kernel(const float* __restrict__ x,
                                  const float* __restrict__ w,
                                  const float* __restrict__ b) {
    int n = blockIdx.x;
    int c = threadIdx.x;
    __shared__ float xs[16];
    if (c < 16) xs[c] = x[n*16 + c];
    __syncthreads();
    float acc = b[c];
#pragma unroll
    for (int k = 0; k < 16; k++) acc = fmaf(xs[k], w[k*HID + c], acc);
    d_h[(size_t)n*HID + c] = acc;
}
// W [K,256] row-major -> hi/lo bf16 [256,K] row-major (transposed + split).
template<int DSEL>
__global__ void transpose_split_kernel(const float* __restrict__ W, int layer, int K) {
    __shared__ float tile[32][33];
    unsigned short *WH, *WL;
    if      constexpr (DSEL == 0) { WH = d_bhi_m1 + (size_t)layer*256*512; WL = d_blo_m1 + (size_t)layer*256*512; }
    else if constexpr (DSEL == 1) { WH = d_bhi_m2 + (size_t)layer*256*256; WL = d_blo_m2 + (size_t)layer*256*256; }
    else if constexpr (DSEL == 2) { WH = d_bhi_u1 + (size_t)layer*256*512; WL = d_blo_u1 + (size_t)layer*256*512; }
    else if constexpr (DSEL == 3) { WH = d_bhi_u2 + (size_t)layer*256*256; WL = d_blo_u2 + (size_t)layer*256*256; }
    else                          { WH = d_bhi_r; WL = d_blo_r; }
    int kb = blockIdx.x*32, nb = blockIdx.y*32;
    for (int r = threadIdx.y; r < 32; r += 8)
        tile[r][threadIdx.x] = W[(size_t)(kb + r)*256 + nb + threadIdx.x];
    __syncthreads();
    for (int r = threadIdx.y; r < 32; r += 8) {
        float v = tile[threadIdx.x][r];
        __nv_bfloat16 hb = __float2bfloat16(v);
        float hf = __bfloat162float(hb);
        __nv_bfloat16 lb = __float2bfloat16(v - hf);
        size_t o = (size_t)(nb + r)*K + kb + threadIdx.x;
        WH[o] = __bfloat16_as_ushort(hb);
        WL[o] = __bfloat16_as_ushort(lb);
    }
}

// ---------------- bf16x3 split mma.sync GEMM: [M,K] @ [K,256] ----------------
// CTA tile 128x256, BK=32, 256 threads, 8 warps (2 M x 4 N), warp tile 64x64.
// A smem fp32, stride 40 floats (160B) -> conflict-free LDS.64 fragments.
// B smem bf16 hi+lo, stride 40 halves (80B) -> conflict-free LDS.32 fragments.
// D = Ahi*Bhi + Ahi*Blo + Alo*Bhi (3x m16n8k16 bf16, fp32 accum).
#define AROWSTR  40
#define BROWSTR  40
#define A_BYTES  (128*AROWSTR*4)       // 20480
#define BH_BYTES (256*BROWSTR*2)       // 20480
#define STAGE_BYTES (A_BYTES + 2*BH_BYTES)  // 61440
#define SMEM_DYN (2*STAGE_BYTES)            // 122880

template<int AMODE, int EPI>
__global__ __launch_bounds__(256, 1)
void tc_gemm(const float* __restrict__ bias,
             const int* __restrict__ srcI, const int* __restrict__ dstI,
             int K, int layer)
{
    extern __shared__ char dynsmem[];
    const uint32_t smem_base = smem_u32(dynsmem);

    const int tid  = threadIdx.x;
    const int lane = tid & 31;
    const int wid  = tid >> 5;
    const int wm   = wid & 1;           // M half (0/1)
    const int wn   = wid >> 1;          // N quarter (0..3)
    const int g    = lane >> 2;         // 0..7
    const int t4   = lane & 3;          // 0..3
    const int row0 = blockIdx.x * 128;

    // weight matrices for this AMODE
    const unsigned short *WH, *WL;
    if      constexpr (AMODE == 2) { WH = d_bhi_m1 + (size_t)layer*256*512; WL = d_blo_m1 + (size_t)layer*256*512; }
    else if constexpr (AMODE == 0) { WH = d_bhi_m2 + (size_t)layer*256*256; WL = d_blo_m2 + (size_t)layer*256*256; }
    else if constexpr (AMODE == 3) { WH = d_bhi_u1 + (size_t)layer*256*512; WL = d_blo_u1 + (size_t)layer*256*512; }
    else if constexpr (AMODE == 1) { WH = d_bhi_u2 + (size_t)layer*256*256; WL = d_blo_u2 + (size_t)layer*256*256; }
    else                           { WH = d_bhi_r; WL = d_blo_r; }

    // ---- cp.async load assignments ----
    const int rt = tid >> 3;            // 0..31 base row
    const int cc = tid & 7;             // A: 16B chunk 0..7 | B: (cc&3) chunk, cc<4 hi / else lo
    uint32_t sAoff[4], sBoff[8];
#pragma unroll
    for (int j = 0; j < 4; j++)
        sAoff[j] = (uint32_t)(rt + j*32)*(AROWSTR*4u) + (uint32_t)cc*16u;
#pragma unroll
    for (int j = 0; j < 8; j++)
        sBoff[j] = (uint32_t)(rt + j*32)*(BROWSTR*2u) + (uint32_t)(cc & 3)*16u;

    // global A element offsets (fp32 elements)
    uint32_t aofs0[4], aofs1[4];
    const float *baseA0, *baseA1;
    if constexpr (AMODE == 0)      { baseA0 = d_t1; baseA1 = d_t1; }
    else if constexpr (AMODE == 1) { baseA0 = d_t2; baseA1 = d_t2; }
    else if constexpr (AMODE == 2) { baseA0 = d_h;  baseA1 = d_h;  }
    else if constexpr (AMODE == 3) { baseA0 = d_h;  baseA1 = d_agg; }
    else                           { baseA0 = d_h;  baseA1 = d_h;  }
#pragma unroll
    for (int j = 0; j < 4; j++) {
        int gr = row0 + rt + j*32;
        if constexpr (AMODE == 0 || AMODE == 1) {
            aofs0[j] = (uint32_t)gr*HID + cc*4u;  aofs1[j] = aofs0[j];
        } else if constexpr (AMODE == 2) {
            aofs0[j] = (uint32_t)dstI[gr]*HID + cc*4u;
            aofs1[j] = (uint32_t)srcI[gr]*HID + cc*4u;
        } else if constexpr (AMODE == 3) {
            aofs0[j] = (uint32_t)gr*HID + cc*4u;  aofs1[j] = aofs0[j];
        } else {
            int gg = gr / 80, bb = gr % 80;
            aofs0[j] = (uint32_t)(gg*NPG + (bb % 57))*HID + cc*4u;
            aofs1[j] = (uint32_t)(gg*NPG + ((bb*13 + 1) % 57))*HID + cc*4u;
        }
    }
    // B: half the threads load hi, half load lo
    const unsigned short* gB = ((cc < 4) ? WH : WL) + (size_t)rt*K + (cc & 3)*8;
    const uint32_t sBsel = (cc < 4) ? 0u : BH_BYTES;

    // ---- accumulators ----
    float acc[4][8][4];
#pragma unroll
    for (int mi = 0; mi < 4; mi++)
#pragma unroll
        for (int ni = 0; ni < 8; ni++)
#pragma unroll
            for (int r = 0; r < 4; r++) acc[mi][ni][r] = 0.f;

    const int NC = K >> 5;

    auto load_chunk = [&](int t, int stage) {
        const int k0 = t*32;
        const int half = k0 >> 8;
        const int kin  = k0 & 255;
        uint32_t sa  = smem_base + (uint32_t)stage*STAGE_BYTES;
        uint32_t sbh = sa + A_BYTES + sBsel;
#pragma unroll
        for (int j = 0; j < 4; j++) {
            const float* src = (half ? baseA1 + aofs1[j] : baseA0 + aofs0[j]) + kin;
            cp_async16(sa + sAoff[j], src);
        }
#pragma unroll
        for (int j = 0; j < 8; j++)
            cp_async16(sbh + sBoff[j], gB + (size_t)j*32*K + k0);
    };

    load_chunk(0, 0);
    CP_COMMIT();

    for (int t = 0; t < NC; t++) {
        if (t + 1 < NC) { load_chunk(t + 1, (t + 1) & 1); CP_COMMIT(); CP_WAIT1(); }
        else            { CP_WAIT0(); }
        __syncthreads();

        const char*  stg = dynsmem + (t & 1)*STAGE_BYTES;
        const float* sA  = (const float*)stg;
        const char*  sBH = stg + A_BYTES;
        const char*  sBL = sBH + BH_BYTES;

#pragma unroll
        for (int ks = 0; ks < 2; ks++) {
            const int kf = ks*16 + t4*2;
            uint32_t ahi[4][4], alo[4][4];
#pragma unroll
            for (int mi = 0; mi < 4; mi++) {
                const float* ap = sA + (wm*64 + mi*16 + g)*AROWSTR + kf;
                float2 v00 = *(const float2*)ap;
                float2 v10 = *(const float2*)(ap + 8*AROWSTR);
                float2 v01 = *(const float2*)(ap + 8);
                float2 v11 = *(const float2*)(ap + 8*AROWSTR + 8);
                split_bf16x2(v00, ahi[mi][0], alo[mi][0]);
                split_bf16x2(v10, ahi[mi][1], alo[mi][1]);
                split_bf16x2(v01, ahi[mi][2], alo[mi][2]);
                split_bf16x2(v11, ahi[mi][3], alo[mi][3]);
            }
#pragma unroll
            for (int ni = 0; ni < 8; ni++) {
                const uint32_t boff = (uint32_t)(wn*64 + ni*8 + g)*(BROWSTR*2u) + (uint32_t)(ks*16 + t4*2)*2u;
                uint32_t bhi[2] = { *(const uint32_t*)(sBH + boff),
                                    *(const uint32_t*)(sBH + boff + 16) };
                uint32_t blo[2] = { *(const uint32_t*)(sBL + boff),
                                    *(const uint32_t*)(sBL + boff + 16) };
#pragma unroll
                for (int mi = 0; mi < 4; mi++) {
                    mma_bf16(acc[mi][ni], ahi[mi], bhi);
                    mma_bf16(acc[mi][ni], ahi[mi], blo);
                    mma_bf16(acc[mi][ni], alo[mi], bhi);
                }
            }
        }
        __syncthreads();
    }

    // ---- epilogue (acc layout: rows g + rh*8, cols t4*2) ----
    const int colb = wn*64 + t4*2;     // + ni*8
    float2 bias2[8];
#pragma unroll
    for (int ni = 0; ni < 8; ni++)
        bias2[ni] = *(const float2*)(bias + colb + ni*8);

    float2 sc2[8], sh2[8];
    if constexpr (EPI == 2) {
#pragma unroll
        for (int ni = 0; ni < 8; ni++) {
            sc2[ni] = *(const float2*)(d_bnscale + layer*HID + colb + ni*8);
            sh2[ni] = *(const float2*)(d_bnshift + layer*HID + colb + ni*8);
        }
    }

#pragma unroll
    for (int mi = 0; mi < 4; mi++) {
#pragma unroll
        for (int rh = 0; rh < 2; rh++) {
            const int row = row0 + wm*64 + mi*16 + g + rh*8;
            if constexpr (EPI == 0) {
                float* out;
                if      constexpr (AMODE == 2) out = d_t1;
                else if constexpr (AMODE == 3) out = d_t2;
                else                           out = d_t3;
                float* op = out + (size_t)row*HID + colb;
#pragma unroll
                for (int ni = 0; ni < 8; ni++) {
                    float v0 = fmaxf(acc[mi][ni][rh*2+0] + bias2[ni].x, 0.f);
                    float v1 = fmaxf(acc[mi][ni][rh*2+1] + bias2[ni].y, 0.f);
                    *(float2*)(op + ni*8) = make_float2(v0, v1);
                }
            } else if constexpr (EPI == 1) {
                const int node = dstI[row];
                float* ap = d_agg + (size_t)node*HID + colb;
#pragma unroll
                for (int ni = 0; ni < 8; ni++)
                    red_add_v2(ap + ni*8,
                               acc[mi][ni][rh*2+0] + bias2[ni].x,
                               acc[mi][ni][rh*2+1] + bias2[ni].y);
            } else {
                float* hp = d_h + (size_t)row*HID + colb;
#pragma unroll
                for (int ni = 0; ni < 8; ni++) {
                    float2 res = *(float2*)(hp + ni*8);
                    float u0 = fmaf(acc[mi][ni][rh*2+0] + bias2[ni].x, sc2[ni].x, sh2[ni].x);
                    float u1 = fmaf(acc[mi][ni][rh*2+1] + bias2[ni].y, sc2[ni].y, sh2[ni].y);
                    *(float2*)(hp + ni*8) = make_float2(fmaxf(u0,0.f) + res.x,
                                                        fmaxf(u1,0.f) + res.y);
                }
            }
        }
    }
}

__global__ void final_dot_kernel(const float* __restrict__ w2,
                                 const float* __restrict__ b2,
                                 float* __restrict__ out) {
    int row  = blockIdx.x*8 + (threadIdx.x >> 5);
    int lane = threadIdx.x & 31;
    const float* t = d_t3 + (size_t)row*HID;
    float s = 0.f;
#pragma unroll
    for (int k = lane; k < HID; k += 32) s = fmaf(t[k], w2[k], s);
#pragma unroll
    for (int o = 16; o > 0; o >>= 1) s += __shfl_down_sync(0xffffffffu, s, o);
    if (lane == 0) out[row] = s + b2[0];
}

// ---------------- launch ----------------
extern "C" void kernel_launch(void* const* d_in, const int* in_sizes, int n_in,
                              void* d_out, int out_size)
{
    const float* x      = (const float*)d_in[0];
    const int*   ei     = (const int*)  d_in[1];
    const float* in_w   = (const float*)d_in[3];
    const float* in_b   = (const float*)d_in[4];
    const float* msg_w1 = (const float*)d_in[5];
    const float* msg_b1 = (const float*)d_in[6];
    const float* msg_w2 = (const float*)d_in[7];
    const float* msg_b2 = (const float*)d_in[8];
    const float* upd_w1 = (const float*)d_in[9];
    const float* upd_b1 = (const float*)d_in[10];
    const float* upd_w2 = (const float*)d_in[11];
    const float* upd_b2 = (const float*)d_in[12];
    const float* bn_g   = (const float*)d_in[13];
    const float* bn_b   = (const float*)d_in[14];
    const float* bn_m   = (const float*)d_in[15];
    const float* bn_v   = (const float*)d_in[16];
    const float* mlp_w1 = (const float*)d_in[17];
    const float* mlp_b1 = (const float*)d_in[18];
    const float* mlp_w2 = (const float*)d_in[19];
    const float* mlp_b2 = (const float*)d_in[20];
    float* out = (float*)d_out;

    const int* srcI = ei;
    const int* dstI = ei + NEDGES;

    cudaFuncSetAttribute(tc_gemm<2,0>, cudaFuncAttributeMaxDynamicSharedMemorySize, SMEM_DYN);
    cudaFuncSetAttribute(tc_gemm<0,1>, cudaFuncAttributeMaxDynamicSharedMemorySize, SMEM_DYN);
    cudaFuncSetAttribute(tc_gemm<3,0>, cudaFuncAttributeMaxDynamicSharedMemorySize, SMEM_DYN);
    cudaFuncSetAttribute(tc_gemm<1,2>, cudaFuncAttributeMaxDynamicSharedMemorySize, SMEM_DYN);
    cudaFuncSetAttribute(tc_gemm<4,0>, cudaFuncAttributeMaxDynamicSharedMemorySize, SMEM_DYN);

    // prep
    deg_zero_kernel <<<(NNODES+255)/256, 256>>>();
    deg_count_kernel<<<(NEDGES+255)/256, 256>>>(dstI);
    deg_inv_kernel  <<<(NNODES+255)/256, 256>>>();
    bn_prep_kernel  <<<(NLAY*HID+255)/256, 256>>>(bn_g, bn_b, bn_m, bn_v);
    input_gemm_kernel<<<NNODES, 256>>>(x, in_w, in_b);

    dim3 tb(32, 8);
    for (int l = 0; l < NLAY; l++) {
        transpose_split_kernel<0><<<dim3(16, 8), tb>>>(msg_w1 + (size_t)l*512*HID, l, 512);
        transpose_split_kernel<1><<<dim3(8,  8), tb>>>(msg_w2 + (size_t)l*HID*HID, l, 256);
        transpose_split_kernel<2><<<dim3(16, 8), tb>>>(upd_w1 + (size_t)l*512*HID, l, 512);
        transpose_split_kernel<3><<<dim3(8,  8), tb>>>(upd_w2 + (size_t)l*HID*HID, l, 256);
    }
    transpose_split_kernel<4><<<dim3(16, 8), tb>>>(mlp_w1, 0, 512);

    for (int l = 0; l < NLAY; l++) {
        zero_agg_kernel<<<2048, 256>>>();
        // message MLP: relu(cat[h[dst],h[src]] @ W1 + b1) -> t1
        tc_gemm<2,0><<<NEDGES/128, 256, SMEM_DYN>>>(msg_b1 + l*HID, srcI, dstI, 512, l);
        // t1 @ W2 + b2 -> red-scatter into agg[dst]
        tc_gemm<0,1><<<NEDGES/128, 256, SMEM_DYN>>>(msg_b2 + l*HID, srcI, dstI, 256, l);
        // agg *= invdeg (mean)
        scale_agg_kernel<<<2048, 256>>>();
        // update MLP: relu(cat[h, agg] @ W1 + b1) -> t2
        tc_gemm<3,0><<<NNODES/128, 256, SMEM_DYN>>>(upd_b1 + l*HID, srcI, dstI, 512, l);
        // t2 @ W2 + b2 -> BN -> relu -> + residual -> h
        tc_gemm<1,2><<<NNODES/128, 256, SMEM_DYN>>>(upd_b2 + l*HID, srcI, dstI, 256, l);
    }

    tc_gemm<4,0><<<NEF/128, 256, SMEM_DYN>>>(mlp_b1, nullptr, nullptr, 512, 0);
    final_dot_kernel<<<NEF/8, 256>>>(mlp_w2, mlp_b2, out);
}

// round 7
// speedup vs baseline: 3.0657x; 1.3416x over previous
#include <cuda_runtime.h>
#include <cuda_bf16.h>
#include <cstdint>

#define GNUM   2048
#define NPG    57
#define NNODES (GNUM*NPG)      // 116736
#define EPG    160
#define NEDGES (GNUM*EPG)      // 327680
#define HID    256
#define NLAY   5
#define NEF    (GNUM*80)       // 163840

// ---------------- scratch (static __device__ arrays; no allocs) ----------------
__device__ float d_h   [(size_t)NNODES*HID];
__device__ float d_t2  [(size_t)NNODES*HID];
__device__ float d_agg [(size_t)NNODES*HID];
__device__ float d_P   [(size_t)NNODES*HID];
__device__ float d_Q   [(size_t)NNODES*HID];
__device__ float d_invdeg [NNODES];
__device__ float d_bnscale[NLAY*HID];
__device__ float d_bnshift[NLAY*HID];
// transposed, bf16-split weights: [256 out, K] K-major, hi + lo parts
__device__ unsigned short d_bhi_m1[(size_t)NLAY*256*512];
__device__ unsigned short d_blo_m1[(size_t)NLAY*256*512];
__device__ unsigned short d_bhi_m2[(size_t)NLAY*256*256];
__device__ unsigned short d_blo_m2[(size_t)NLAY*256*256];
__device__ unsigned short d_bhi_u1[(size_t)NLAY*256*512];
__device__ unsigned short d_blo_u1[(size_t)NLAY*256*512];
__device__ unsigned short d_bhi_u2[(size_t)NLAY*256*256];
__device__ unsigned short d_blo_u2[(size_t)NLAY*256*256];
__device__ unsigned short d_bhi_r [(size_t)256*512];
__device__ unsigned short d_blo_r [(size_t)256*512];

// ---------------- PTX helpers (family-target-safe) ----------------
__device__ __forceinline__ uint32_t smem_u32(const void* p) {
    uint32_t a;
    asm("{ .reg .u64 t; cvta.to.shared.u64 t, %1; cvt.u32.u64 %0, t; }" : "=r"(a) : "l"(p));
    return a;
}
__device__ __forceinline__ void cp_async16(uint32_t smem, const void* g) {
    asm volatile("cp.async.cg.shared.global [%0], [%1], 16;" :: "r"(smem), "l"(g) : "memory");
}
#define CP_COMMIT() asm volatile("cp.async.commit_group;" ::: "memory")
#define CP_WAIT1()  asm volatile("cp.async.wait_group 1;" ::: "memory")
#define CP_WAIT0()  asm volatile("cp.async.wait_group 0;" ::: "memory")

__device__ __forceinline__ void mma_bf16(float* d, const uint32_t* a, const uint32_t* b) {
    asm volatile(
        "mma.sync.aligned.m16n8k16.row.col.f32.bf16.bf16.f32 "
        "{%0,%1,%2,%3}, {%4,%5,%6,%7}, {%8,%9}, {%0,%1,%2,%3};"
        : "+f"(d[0]), "+f"(d[1]), "+f"(d[2]), "+f"(d[3])
        : "r"(a[0]), "r"(a[1]), "r"(a[2]), "r"(a[3]), "r"(b[0]), "r"(b[1]));
}
__device__ __forceinline__ void red_add_v2(float* p, float a, float b) {
    asm volatile("red.global.add.v2.f32 [%0], {%1, %2};"
                 :: "l"(p), "f"(a), "f"(b) : "memory");
}
__device__ __forceinline__ void split_bf16x2(float2 v, uint32_t& hi, uint32_t& lo) {
    asm("cvt.rn.bf16x2.f32 %0, %1, %2;" : "=r"(hi) : "f"(v.y), "f"(v.x));
    float hlo = __uint_as_float(hi << 16);
    float hhi = __uint_as_float(hi & 0xFFFF0000u);
    asm("cvt.rn.bf16x2.f32 %0, %1, %2;" : "=r"(lo) : "f"(v.y - hhi), "f"(v.x - hlo));
}
#define STS128U(addr, r0, r1, r2, r3) \
    asm volatile("st.shared.v4.b32 [%0], {%1, %2, %3, %4};" \
                 :: "r"(addr), "r"(r0), "r"(r1), "r"(r2), "r"(r3) : "memory")

// ---------------- small helper kernels ----------------
__global__ void zero_agg_kernel() {
    size_t n4 = (size_t)NNODES*HID/4;
    float4 z = make_float4(0.f,0.f,0.f,0.f);
    for (size_t i = (size_t)blockIdx.x*blockDim.x + threadIdx.x; i < n4;
         i += (size_t)gridDim.x*blockDim.x)
        ((float4*)d_agg)[i] = z;
}
__global__ void scale_agg_kernel() {
    size_t n4 = (size_t)NNODES*HID/4;
    for (size_t i = (size_t)blockIdx.x*blockDim.x + threadIdx.x; i < n4;
         i += (size_t)gridDim.x*blockDim.x) {
        int row = (int)(i >> 6);
        float s = d_invdeg[row];
        float4 v = ((float4*)d_agg)[i];
        v.x*=s; v.y*=s; v.z*=s; v.w*=s;
        ((float4*)d_agg)[i] = v;
    }
}
__global__ void deg_zero_kernel() {
    int i = blockIdx.x*blockDim.x + threadIdx.x;
    if (i < NNODES) d_invdeg[i] = 0.f;
}
__global__ void deg_count_kernel(const int* __restrict__ dst) {
    int e = blockIdx.x*blockDim.x + threadIdx.x;
    if (e < NEDGES) atomicAdd(&d_invdeg[dst[e]], 1.f);
}
__global__ void deg_inv_kernel() {
    int i = blockIdx.x*blockDim.x + threadIdx.x;
    if (i < NNODES) d_invdeg[i] = 1.f / fmaxf(d_invdeg[i], 1.f);
}
__global__ void bn_prep_kernel(const float* __restrict__ g, const float* __restrict__ b,
                               const float* __restrict__ m, const float* __restrict__ v) {
    int i = blockIdx.x*blockDim.x + threadIdx.x;
    if (i < NLAY*HID) {
        float sc = g[i] * rsqrtf(v[i] + 1e-5f);
        d_bnscale[i] = sc;
        d_bnshift[i] = b[i] - m[i]*sc;
    }
}
__global__ void input_gemm_kernel(const float* __restrict__ x,
                                  const float* __restrict__ w,
                                  const float* __restrict__ b) {
    int n = blockIdx.x;
    int c = threadIdx.x;
    __shared__ float xs[16];
    if (c < 16) xs[c] = x[n*16 + c];
    __syncthreads();
    float acc = b[c];
#pragma unroll
    for (int k = 0; k < 16; k++) acc = fmaf(xs[k], w[k*HID + c], acc);
    d_h[(size_t)n*HID + c] = acc;
}
// W [K,256] row-major -> hi/lo bf16 [256,K] row-major (transposed + split).
template<int DSEL>
__global__ void transpose_split_kernel(const float* __restrict__ W, int layer, int K) {
    __shared__ float tile[32][33];
    unsigned short *WH, *WL;
    if      constexpr (DSEL == 0) { WH = d_bhi_m1 + (size_t)layer*256*512; WL = d_blo_m1 + (size_t)layer*256*512; }
    else if constexpr (DSEL == 1) { WH = d_bhi_m2 + (size_t)layer*256*256; WL = d_blo_m2 + (size_t)layer*256*256; }
    else if constexpr (DSEL == 2) { WH = d_bhi_u1 + (size_t)layer*256*512; WL = d_blo_u1 + (size_t)layer*256*512; }
    else if constexpr (DSEL == 3) { WH = d_bhi_u2 + (size_t)layer*256*256; WL = d_blo_u2 + (size_t)layer*256*256; }
    else                          { WH = d_bhi_r; WL = d_blo_r; }
    int kb = blockIdx.x*32, nb = blockIdx.y*32;
    for (int r = threadIdx.y; r < 32; r += 8)
        tile[r][threadIdx.x] = W[(size_t)(kb + r)*256 + nb + threadIdx.x];
    __syncthreads();
    for (int r = threadIdx.y; r < 32; r += 8) {
        float v = tile[threadIdx.x][r];
        __nv_bfloat16 hb = __float2bfloat16(v);
        float hf = __bfloat162float(hb);
        __nv_bfloat16 lb = __float2bfloat16(v - hf);
        size_t o = (size_t)(nb + r)*K + kb + threadIdx.x;
        WH[o] = __bfloat16_as_ushort(hb);
        WL[o] = __bfloat16_as_ushort(lb);
    }
}

// ---------------- bf16x3 split mma.sync GEMM: [M,K] @ [K,256] ----------------
// CTA tile 128x256, BK=32, 256 threads, 8 warps (2 M x 4 N), warp tile 64x64.
// AMODE: 0 = A = Ain rows (K<=256, cp.async)
//        1 = A = concat(Ain[row], Ain2[row]) (K=512, cp.async)
//        2 = A = relu(P[dst]+Q[src]+b1) fused on the fly (K=256, LDG->STS)
// EPI:   0 = relu(acc+bias) -> outp    | 1 = acc+bias -> red.add into d_agg[dst]
//        2 = acc+bias -> BN -> relu -> += d_h -> d_h   | 3 = acc -> outp (raw)
#define AROWSTR  40
#define BROWSTR  40
#define A_BYTES  (128*AROWSTR*4)       // 20480
#define BH_BYTES (256*BROWSTR*2)       // 20480
#define STAGE_BYTES (A_BYTES + 2*BH_BYTES)  // 61440
#define SMEM_DYN (2*STAGE_BYTES)            // 122880

template<int AMODE, int EPI>
__global__ __launch_bounds__(256, 1)
void tc_gemm(const unsigned short* __restrict__ WH, const unsigned short* __restrict__ WL,
             int ldB,
             const float* __restrict__ bias,   // output-side bias (EPI 0/1/2)
             float* __restrict__ outp,         // EPI 0/3 destination
             const float* __restrict__ Ain, const float* __restrict__ Ain2,
             const float* __restrict__ b1,     // AMODE2 inner bias
             const int* __restrict__ srcI, const int* __restrict__ dstI,
             int K, int layer)
{
    extern __shared__ char dynsmem[];
    const uint32_t smem_base = smem_u32(dynsmem);

    const int tid  = threadIdx.x;
    const int lane = tid & 31;
    const int wid  = tid >> 5;
    const int wm   = wid & 1;           // M half (0/1)
    const int wn   = wid >> 1;          // N quarter (0..3)
    const int g    = lane >> 2;         // 0..7
    const int t4   = lane & 3;          // 0..3
    const int row0 = blockIdx.x * 128;

    // ---- load assignments ----
    const int rt = tid >> 3;            // 0..31 base row
    const int cc = tid & 7;
    uint32_t sAoff[4], sBoff[8];
#pragma unroll
    for (int j = 0; j < 4; j++)
        sAoff[j] = (uint32_t)(rt + j*32)*(AROWSTR*4u) + (uint32_t)cc*16u;
#pragma unroll
    for (int j = 0; j < 8; j++)
        sBoff[j] = (uint32_t)(rt + j*32)*(BROWSTR*2u) + (uint32_t)(cc & 3)*16u;

    // A global offsets
    uint32_t aofs[4], qofs[4];
#pragma unroll
    for (int j = 0; j < 4; j++) {
        int gr = row0 + rt + j*32;
        if constexpr (AMODE == 2) {
            aofs[j] = (uint32_t)dstI[gr]*HID + cc*4u;   // P rows
            qofs[j] = (uint32_t)srcI[gr]*HID + cc*4u;   // Q rows
        } else {
            aofs[j] = (uint32_t)gr*HID + cc*4u;
            qofs[j] = aofs[j];
        }
    }
    // B: half the threads load hi, half load lo
    const unsigned short* gB = ((cc < 4) ? WH : WL) + (size_t)rt*ldB + (cc & 3)*8;
    const uint32_t sBsel = (cc < 4) ? 0u : BH_BYTES;

    float acc[4][8][4];
#pragma unroll
    for (int mi = 0; mi < 4; mi++)
#pragma unroll
        for (int ni = 0; ni < 8; ni++)
#pragma unroll
            for (int r = 0; r < 4; r++) acc[mi][ni][r] = 0.f;

    const int NC = K >> 5;

    auto loadB = [&](int t, int stage) {
        const int k0 = t*32;
        uint32_t sbh = smem_base + (uint32_t)stage*STAGE_BYTES + A_BYTES + sBsel;
#pragma unroll
        for (int j = 0; j < 8; j++)
            cp_async16(sbh + sBoff[j], gB + (size_t)j*32*ldB + k0);
    };
    auto loadA_cp = [&](int t, int stage) {
        const int k0 = t*32;
        uint32_t sa = smem_base + (uint32_t)stage*STAGE_BYTES;
#pragma unroll
        for (int j = 0; j < 4; j++) {
            const float* src;
            if constexpr (AMODE == 1) {
                const int half = k0 >> 8, kin = k0 & 255;
                src = (half ? Ain2 : Ain) + aofs[j] + kin;
            } else {
                src = Ain + aofs[j] + k0;
            }
            cp_async16(sa + sAoff[j], src);
        }
    };

    // compute one 32-k chunk from smem stage
    auto compute = [&](int stage) {
        const char*  stg = dynsmem + stage*STAGE_BYTES;
        const float* sA  = (const float*)stg;
        const char*  sBH = stg + A_BYTES;
        const char*  sBL = sBH + BH_BYTES;
#pragma unroll
        for (int ks = 0; ks < 2; ks++) {
            const int kf = ks*16 + t4*2;
            uint32_t ahi[4][4], alo[4][4];
#pragma unroll
            for (int mi = 0; mi < 4; mi++) {
                const float* ap = sA + (wm*64 + mi*16 + g)*AROWSTR + kf;
                float2 v00 = *(const float2*)ap;
                float2 v10 = *(const float2*)(ap + 8*AROWSTR);
                float2 v01 = *(const float2*)(ap + 8);
                float2 v11 = *(const float2*)(ap + 8*AROWSTR + 8);
                split_bf16x2(v00, ahi[mi][0], alo[mi][0]);
                split_bf16x2(v10, ahi[mi][1], alo[mi][1]);
                split_bf16x2(v01, ahi[mi][2], alo[mi][2]);
                split_bf16x2(v11, ahi[mi][3], alo[mi][3]);
            }
#pragma unroll
            for (int ni = 0; ni < 8; ni++) {
                const uint32_t boff = (uint32_t)(wn*64 + ni*8 + g)*(BROWSTR*2u)
                                    + (uint32_t)(ks*16 + t4*2)*2u;
                uint32_t bhi[2] = { *(const uint32_t*)(sBH + boff),
                                    *(const uint32_t*)(sBH + boff + 16) };
                uint32_t blo[2] = { *(const uint32_t*)(sBL + boff),
                                    *(const uint32_t*)(sBL + boff + 16) };
#pragma unroll
                for (int mi = 0; mi < 4; mi++) {
                    mma_bf16(acc[mi][ni], ahi[mi], bhi);
                    mma_bf16(acc[mi][ni], ahi[mi], blo);
                    mma_bf16(acc[mi][ni], alo[mi], bhi);
                }
            }
        }
    };

    if constexpr (AMODE == 2) {
        // register-staged A (LDG -> combine -> STS), cp.async B
        float4 pv[4], qv[4], bv;
        auto ldgA = [&](int t) {
            const int k0 = t*32;
            bv = *(const float4*)(b1 + k0 + cc*4);
#pragma unroll
            for (int j = 0; j < 4; j++) {
                pv[j] = *(const float4*)(Ain  + aofs[j] + k0);
                qv[j] = *(const float4*)(Ain2 + qofs[j] + k0);
            }
        };
        auto stsA = [&](int stage) {
            uint32_t sa = smem_base + (uint32_t)stage*STAGE_BYTES;
#pragma unroll
            for (int j = 0; j < 4; j++) {
                float v0 = fmaxf(pv[j].x + qv[j].x + bv.x, 0.f);
                float v1 = fmaxf(pv[j].y + qv[j].y + bv.y, 0.f);
                float v2 = fmaxf(pv[j].z + qv[j].z + bv.z, 0.f);
                float v3 = fmaxf(pv[j].w + qv[j].w + bv.w, 0.f);
                STS128U(sa + sAoff[j], __float_as_uint(v0), __float_as_uint(v1),
                                       __float_as_uint(v2), __float_as_uint(v3));
            }
        };
        ldgA(0);
        loadB(0, 0); CP_COMMIT();
        for (int t = 0; t < NC; t++) {
            stsA(t & 1);
            if (t + 1 < NC) { ldgA(t + 1); loadB(t + 1, (t + 1) & 1); CP_COMMIT(); CP_WAIT1(); }
            else            { CP_WAIT0(); }
            __syncthreads();
            compute(t & 1);
            __syncthreads();
        }
    } else {
        loadA_cp(0, 0); loadB(0, 0); CP_COMMIT();
        for (int t = 0; t < NC; t++) {
            if (t + 1 < NC) {
                loadA_cp(t + 1, (t + 1) & 1); loadB(t + 1, (t + 1) & 1);
                CP_COMMIT(); CP_WAIT1();
            } else CP_WAIT0();
            __syncthreads();
            compute(t & 1);
            __syncthreads();
        }
    }

    // ---- epilogue (acc rows g + rh*8, cols t4*2 + ni*8) ----
    const int colb = wn*64 + t4*2;
    float2 bias2[8];
    if constexpr (EPI != 3) {
#pragma unroll
        for (int ni = 0; ni < 8; ni++)
            bias2[ni] = *(const float2*)(bias + colb + ni*8);
    }
    float2 sc2[8], sh2[8];
    if constexpr (EPI == 2) {
#pragma unroll
        for (int ni = 0; ni < 8; ni++) {
            sc2[ni] = *(const float2*)(d_bnscale + layer*HID + colb + ni*8);
            sh2[ni] = *(const float2*)(d_bnshift + layer*HID + colb + ni*8);
        }
    }

#pragma unroll
    for (int mi = 0; mi < 4; mi++) {
#pragma unroll
        for (int rh = 0; rh < 2; rh++) {
            const int row = row0 + wm*64 + mi*16 + g + rh*8;
            if constexpr (EPI == 0) {
                float* op = outp + (size_t)row*HID + colb;
#pragma unroll
                for (int ni = 0; ni < 8; ni++) {
                    float v0 = fmaxf(acc[mi][ni][rh*2+0] + bias2[ni].x, 0.f);
                    float v1 = fmaxf(acc[mi][ni][rh*2+1] + bias2[ni].y, 0.f);
                    *(float2*)(op + ni*8) = make_float2(v0, v1);
                }
            } else if constexpr (EPI == 3) {
                float* op = outp + (size_t)row*HID + colb;
#pragma unroll
                for (int ni = 0; ni < 8; ni++)
                    *(float2*)(op + ni*8) = make_float2(acc[mi][ni][rh*2+0],
                                                        acc[mi][ni][rh*2+1]);
            } else if constexpr (EPI == 1) {
                const int node = dstI[row];
                float* ap = d_agg + (size_t)node*HID + colb;
#pragma unroll
                for (int ni = 0; ni < 8; ni++)
                    red_add_v2(ap + ni*8,
                               acc[mi][ni][rh*2+0] + bias2[ni].x,
                               acc[mi][ni][rh*2+1] + bias2[ni].y);
            } else {
                float* hp = d_h + (size_t)row*HID + colb;
#pragma unroll
                for (int ni = 0; ni < 8; ni++) {
                    float2 res = *(float2*)(hp + ni*8);
                    float u0 = fmaf(acc[mi][ni][rh*2+0] + bias2[ni].x, sc2[ni].x, sh2[ni].x);
                    float u1 = fmaf(acc[mi][ni][rh*2+1] + bias2[ni].y, sc2[ni].y, sh2[ni].y);
                    *(float2*)(hp + ni*8) = make_float2(fmaxf(u0,0.f) + res.x,
                                                        fmaxf(u1,0.f) + res.y);
                }
            }
        }
    }
}

// out[row] = relu(R[u]+S[v]+b1) . w2 + b2   (readout, no GEMM needed)
__global__ void final_pair_dot_kernel(const float* __restrict__ b1,
                                      const float* __restrict__ w2,
                                      const float* __restrict__ b2,
                                      float* __restrict__ out) {
    int row  = blockIdx.x*8 + (threadIdx.x >> 5);
    int lane = threadIdx.x & 31;
    int gg = row / 80, bb = row % 80;
    const float* R = d_P + (size_t)(gg*NPG + (bb % 57))*HID;
    const float* S = d_Q + (size_t)(gg*NPG + ((bb*13 + 1) % 57))*HID;
    float s = 0.f;
#pragma unroll
    for (int k = lane; k < HID; k += 32) {
        float v = fmaxf(R[k] + S[k] + __ldg(b1 + k), 0.f);
        s = fmaf(v, __ldg(w2 + k), s);
    }
#pragma unroll
    for (int o = 16; o > 0; o >>= 1) s += __shfl_down_sync(0xffffffffu, s, o);
    if (lane == 0) out[row] = s + b2[0];
}

// ---------------- launch ----------------
extern "C" void kernel_launch(void* const* d_in, const int* in_sizes, int n_in,
                              void* d_out, int out_size)
{
    const float* x      = (const float*)d_in[0];
    const int*   ei     = (const int*)  d_in[1];
    const float* in_w   = (const float*)d_in[3];
    const float* in_b   = (const float*)d_in[4];
    const float* msg_w1 = (const float*)d_in[5];
    const float* msg_b1 = (const float*)d_in[6];
    const float* msg_w2 = (const float*)d_in[7];
    const float* msg_b2 = (const float*)d_in[8];
    const float* upd_w1 = (const float*)d_in[9];
    const float* upd_b1 = (const float*)d_in[10];
    const float* upd_w2 = (const float*)d_in[11];
    const float* upd_b2 = (const float*)d_in[12];
    const float* bn_g   = (const float*)d_in[13];
    const float* bn_b   = (const float*)d_in[14];
    const float* bn_m   = (const float*)d_in[15];
    const float* bn_v   = (const float*)d_in[16];
    const float* mlp_w1 = (const float*)d_in[17];
    const float* mlp_b1 = (const float*)d_in[18];
    const float* mlp_w2 = (const float*)d_in[19];
    const float* mlp_b2 = (const float*)d_in[20];
    float* out = (float*)d_out;

    const int* srcI = ei;
    const int* dstI = ei + NEDGES;

    cudaFuncSetAttribute(tc_gemm<0,3>, cudaFuncAttributeMaxDynamicSharedMemorySize, SMEM_DYN);
    cudaFuncSetAttribute(tc_gemm<2,1>, cudaFuncAttributeMaxDynamicSharedMemorySize, SMEM_DYN);
    cudaFuncSetAttribute(tc_gemm<1,0>, cudaFuncAttributeMaxDynamicSharedMemorySize, SMEM_DYN);
    cudaFuncSetAttribute(tc_gemm<0,2>, cudaFuncAttributeMaxDynamicSharedMemorySize, SMEM_DYN);

    // device pointers to __device__ globals (host side must use symbol addresses)
    float *pP, *pQ, *pH, *pT2, *pAgg;
    cudaGetSymbolAddress((void**)&pP,  d_P);
    cudaGetSymbolAddress((void**)&pQ,  d_Q);
    cudaGetSymbolAddress((void**)&pH,  d_h);
    cudaGetSymbolAddress((void**)&pT2, d_t2);
    cudaGetSymbolAddress((void**)&pAgg,d_agg);
    unsigned short *pHm1,*pLm1,*pHm2,*pLm2,*pHu1,*pLu1,*pHu2,*pLu2,*pHr,*pLr;
    cudaGetSymbolAddress((void**)&pHm1, d_bhi_m1); cudaGetSymbolAddress((void**)&pLm1, d_blo_m1);
    cudaGetSymbolAddress((void**)&pHm2, d_bhi_m2); cudaGetSymbolAddress((void**)&pLm2, d_blo_m2);
    cudaGetSymbolAddress((void**)&pHu1, d_bhi_u1); cudaGetSymbolAddress((void**)&pLu1, d_blo_u1);
    cudaGetSymbolAddress((void**)&pHu2, d_bhi_u2); cudaGetSymbolAddress((void**)&pLu2, d_blo_u2);
    cudaGetSymbolAddress((void**)&pHr,  d_bhi_r ); cudaGetSymbolAddress((void**)&pLr,  d_blo_r );

    // prep
    deg_zero_kernel <<<(NNODES+255)/256, 256>>>();
    deg_count_kernel<<<(NEDGES+255)/256, 256>>>(dstI);
    deg_inv_kernel  <<<(NNODES+255)/256, 256>>>();
    bn_prep_kernel  <<<(NLAY*HID+255)/256, 256>>>(bn_g, bn_b, bn_m, bn_v);
    input_gemm_kernel<<<NNODES, 256>>>(x, in_w, in_b);

    dim3 tb(32, 8);
    for (int l = 0; l < NLAY; l++) {
        transpose_split_kernel<0><<<dim3(16, 8), tb>>>(msg_w1 + (size_t)l*512*HID, l, 512);
        transpose_split_kernel<1><<<dim3(8,  8), tb>>>(msg_w2 + (size_t)l*HID*HID, l, 256);
        transpose_split_kernel<2><<<dim3(16, 8), tb>>>(upd_w1 + (size_t)l*512*HID, l, 512);
        transpose_split_kernel<3><<<dim3(8,  8), tb>>>(upd_w2 + (size_t)l*HID*HID, l, 256);
    }
    transpose_split_kernel<4><<<dim3(16, 8), tb>>>(mlp_w1, 0, 512);

    const int NGRID = NNODES/128;   // 912
    const int EGRID = NEDGES/128;   // 2560

    for (int l = 0; l < NLAY; l++) {
        const size_t o1 = (size_t)l*256*512;
        const size_t o2 = (size_t)l*256*256;
        zero_agg_kernel<<<2048, 256>>>();
        // P = h @ W1_top  (cols 0..255 of transposed W1, ld 512)
        tc_gemm<0,3><<<NGRID, 256, SMEM_DYN>>>(pHm1 + o1, pLm1 + o1, 512,
            nullptr, pP, pH, nullptr, nullptr, nullptr, nullptr, 256, l);
        // Q = h @ W1_bot  (cols 256..511)
        tc_gemm<0,3><<<NGRID, 256, SMEM_DYN>>>(pHm1 + o1 + 256, pLm1 + o1 + 256, 512,
            nullptr, pQ, pH, nullptr, nullptr, nullptr, nullptr, 256, l);
        // edges: relu(P[dst]+Q[src]+b1) @ W2 + b2 -> red-scatter into agg[dst]
        tc_gemm<2,1><<<EGRID, 256, SMEM_DYN>>>(pHm2 + o2, pLm2 + o2, 256,
            msg_b2 + l*HID, nullptr, pP, pQ, msg_b1 + l*HID, srcI, dstI, 256, l);
        // agg *= invdeg (mean)
        scale_agg_kernel<<<2048, 256>>>();
        // t2 = relu(concat(h, agg) @ updW1 + b1)
        tc_gemm<1,0><<<NGRID, 256, SMEM_DYN>>>(pHu1 + o1, pLu1 + o1, 512,
            upd_b1 + l*HID, pT2, pH, pAgg, nullptr, nullptr, nullptr, 512, l);
        // h = relu(BN(t2 @ updW2 + b2)) + h
        tc_gemm<0,2><<<NGRID, 256, SMEM_DYN>>>(pHu2 + o2, pLu2 + o2, 256,
            upd_b2 + l*HID, nullptr, pT2, nullptr, nullptr, nullptr, nullptr, 256, l);
    }

    // readout: R = h @ mlpW1_top, S = h @ mlpW1_bot, then fused pair-dot
    tc_gemm<0,3><<<NGRID, 256, SMEM_DYN>>>(pHr, pLr, 512,
        nullptr, pP, pH, nullptr, nullptr, nullptr, nullptr, 256, 0);
    tc_gemm<0,3><<<NGRID, 256, SMEM_DYN>>>(pHr + 256, pLr + 256, 512,
        nullptr, pQ, pH, nullptr, nullptr, nullptr, nullptr, 256, 0);
    final_pair_dot_kernel<<<NEF/8, 256>>>(mlp_b1, mlp_w2, mlp_b2, out);
}

// round 8
// speedup vs baseline: 3.9058x; 1.2740x over previous
#include <cuda_runtime.h>
#include <cuda_bf16.h>
#include <cstdint>

#define GNUM   2048
#define NPG    57
#define NNODES (GNUM*NPG)      // 116736
#define EPG    160
#define NEDGES (GNUM*EPG)      // 327680
#define HID    256
#define NLAY   5
#define NEF    (GNUM*80)       // 163840

// ---------------- scratch (static __device__ arrays; no allocs) ----------------
__device__ float d_h   [(size_t)NNODES*HID];
__device__ float d_t2  [(size_t)NNODES*HID];
__device__ float d_agg [(size_t)NNODES*HID];   // S accumulator
__device__ float d_P   [(size_t)NNODES*HID];
__device__ float d_Q   [(size_t)NNODES*HID];
__device__ float d_invdeg [NNODES];
__device__ float d_b2f    [NNODES];            // 1 if deg>0 else 0
__device__ float d_bnscale[NLAY*HID];
__device__ float d_bnshift[NLAY*HID];
__device__ float d_wcf [(size_t)256*256];      // C_l fp32 staging
__device__ float d_cvec[(size_t)NLAY*HID];     // msg_b2 @ U1bot
// transposed, bf16-split weights: [256 out, K] K-major, hi + lo parts
__device__ unsigned short d_bhi_m1[(size_t)NLAY*256*512];
__device__ unsigned short d_blo_m1[(size_t)NLAY*256*512];
__device__ unsigned short d_bhi_u1[(size_t)NLAY*256*512];
__device__ unsigned short d_blo_u1[(size_t)NLAY*256*512];
__device__ unsigned short d_bhi_u2[(size_t)NLAY*256*256];
__device__ unsigned short d_blo_u2[(size_t)NLAY*256*256];
__device__ unsigned short d_bhi_c [(size_t)NLAY*256*256];   // C_l = W2@U1bot split
__device__ unsigned short d_blo_c [(size_t)NLAY*256*256];
__device__ unsigned short d_bhi_r [(size_t)256*512];
__device__ unsigned short d_blo_r [(size_t)256*512];

// ---------------- PTX helpers (family-target-safe) ----------------
__device__ __forceinline__ uint32_t smem_u32(const void* p) {
    uint32_t a;
    asm("{ .reg .u64 t; cvta.to.shared.u64 t, %1; cvt.u32.u64 %0, t; }" : "=r"(a) : "l"(p));
    return a;
}
__device__ __forceinline__ void cp_async16(uint32_t smem, const void* g) {
    asm volatile("cp.async.cg.shared.global [%0], [%1], 16;" :: "r"(smem), "l"(g) : "memory");
}
#define CP_COMMIT() asm volatile("cp.async.commit_group;" ::: "memory")
#define CP_WAIT1()  asm volatile("cp.async.wait_group 1;" ::: "memory")
#define CP_WAIT0()  asm volatile("cp.async.wait_group 0;" ::: "memory")

__device__ __forceinline__ void mma_bf16(float* d, const uint32_t* a, const uint32_t* b) {
    asm volatile(
        "mma.sync.aligned.m16n8k16.row.col.f32.bf16.bf16.f32 "
        "{%0,%1,%2,%3}, {%4,%5,%6,%7}, {%8,%9}, {%0,%1,%2,%3};"
        : "+f"(d[0]), "+f"(d[1]), "+f"(d[2]), "+f"(d[3])
        : "r"(a[0]), "r"(a[1]), "r"(a[2]), "r"(a[3]), "r"(b[0]), "r"(b[1]));
}
__device__ __forceinline__ void red_add_v4(float* p, float a, float b, float c, float d) {
    asm volatile("red.global.add.v4.f32 [%0], {%1, %2, %3, %4};"
                 :: "l"(p), "f"(a), "f"(b), "f"(c), "f"(d) : "memory");
}
__device__ __forceinline__ void split_bf16x2(float2 v, uint32_t& hi, uint32_t& lo) {
    asm("cvt.rn.bf16x2.f32 %0, %1, %2;" : "=r"(hi) : "f"(v.y), "f"(v.x));
    float hlo = __uint_as_float(hi << 16);
    float hhi = __uint_as_float(hi & 0xFFFF0000u);
    asm("cvt.rn.bf16x2.f32 %0, %1, %2;" : "=r"(lo) : "f"(v.y - hhi), "f"(v.x - hlo));
}

// ---------------- small helper kernels ----------------
__global__ void zero_agg_kernel() {
    size_t n4 = (size_t)NNODES*HID/4;
    float4 z = make_float4(0.f,0.f,0.f,0.f);
    for (size_t i = (size_t)blockIdx.x*blockDim.x + threadIdx.x; i < n4;
         i += (size_t)gridDim.x*blockDim.x)
        ((float4*)d_agg)[i] = z;
}
__global__ void deg_zero_kernel() {
    int i = blockIdx.x*blockDim.x + threadIdx.x;
    if (i < NNODES) d_invdeg[i] = 0.f;
}
__global__ void deg_count_kernel(const int* __restrict__ dst) {
    int e = blockIdx.x*blockDim.x + threadIdx.x;
    if (e < NEDGES) atomicAdd(&d_invdeg[dst[e]], 1.f);
}
__global__ void deg_inv_kernel() {
    int i = blockIdx.x*blockDim.x + threadIdx.x;
    if (i < NNODES) {
        float c = d_invdeg[i];
        d_invdeg[i] = 1.f / fmaxf(c, 1.f);
        d_b2f[i] = (c > 0.f) ? 1.f : 0.f;
    }
}
__global__ void bn_prep_kernel(const float* __restrict__ g, const float* __restrict__ b,
                               const float* __restrict__ m, const float* __restrict__ v) {
    int i = blockIdx.x*blockDim.x + threadIdx.x;
    if (i < NLAY*HID) {
        float sc = g[i] * rsqrtf(v[i] + 1e-5f);
        d_bnscale[i] = sc;
        d_bnshift[i] = b[i] - m[i]*sc;
    }
}
__global__ void input_gemm_kernel(const float* __restrict__ x,
                                  const float* __restrict__ w,
                                  const float* __restrict__ b) {
    int n = blockIdx.x;
    int c = threadIdx.x;
    __shared__ float xs[16];
    if (c < 16) xs[c] = x[n*16 + c];
    __syncthreads();
    float acc = b[c];
#pragma unroll
    for (int k = 0; k < 16; k++) acc = fmaf(xs[k], w[k*HID + c], acc);
    d_h[(size_t)n*HID + c] = acc;
}
// cvec[n] = sum_k b2[k] * U1[256+k][n]   (b2 @ U1bot)
__global__ void cvec_kernel(const float* __restrict__ b2,
                            const float* __restrict__ u1,  // upd_w1 layer: [512,256]
                            float* __restrict__ outc) {
    int n = threadIdx.x;
    float s = 0.f;
    for (int k = 0; k < 256; k++)
        s = fmaf(b2[k], u1[(size_t)(256 + k)*256 + n], s);
    outc[n] = s;
}
// W [K,256] row-major -> hi/lo bf16 [256,K] row-major (transposed + split).
// DSEL: 0=msg_w1  2=upd_w1  3=upd_w2  4=mlp_w1  5=C_l (from d_wcf)
template<int DSEL>
__global__ void transpose_split_kernel(const float* __restrict__ W, int layer, int K) {
    __shared__ float tile[32][33];
    unsigned short *WH, *WL;
    if      constexpr (DSEL == 0) { WH = d_bhi_m1 + (size_t)layer*256*512; WL = d_blo_m1 + (size_t)layer*256*512; }
    else if constexpr (DSEL == 2) { WH = d_bhi_u1 + (size_t)layer*256*512; WL = d_blo_u1 + (size_t)layer*256*512; }
    else if constexpr (DSEL == 3) { WH = d_bhi_u2 + (size_t)layer*256*256; WL = d_blo_u2 + (size_t)layer*256*256; }
    else if constexpr (DSEL == 5) { WH = d_bhi_c  + (size_t)layer*256*256; WL = d_blo_c  + (size_t)layer*256*256; }
    else                          { WH = d_bhi_r; WL = d_blo_r; }
    int kb = blockIdx.x*32, nb = blockIdx.y*32;
    for (int r = threadIdx.y; r < 32; r += 8)
        tile[r][threadIdx.x] = W[(size_t)(kb + r)*256 + nb + threadIdx.x];
    __syncthreads();
    for (int r = threadIdx.y; r < 32; r += 8) {
        float v = tile[threadIdx.x][r];
        __nv_bfloat16 hb = __float2bfloat16(v);
        float hf = __bfloat162float(hb);
        __nv_bfloat16 lb = __float2bfloat16(v - hf);
        size_t o = (size_t)(nb + r)*K + kb + threadIdx.x;
        WH[o] = __bfloat16_as_ushort(hb);
        WL[o] = __bfloat16_as_ushort(lb);
    }
}

// edge scatter: S[dst] += relu(P'[dst] + Q[src])   (P' has msg_b1 folded in)
__global__ __launch_bounds__(256, 8)
void edge_scatter_kernel(const int* __restrict__ srcI, const int* __restrict__ dstI) {
    int e    = blockIdx.x*8 + (threadIdx.x >> 5);
    int lane = threadIdx.x & 31;
    int s = __ldg(srcI + e), d = __ldg(dstI + e);
    const float4* Pp = (const float4*)(d_P + (size_t)d*HID);
    const float4* Qp = (const float4*)(d_Q + (size_t)s*HID);
    float* Sp = d_agg + (size_t)d*HID;
#pragma unroll
    for (int j = 0; j < 2; j++) {
        int idx = lane + j*32;
        float4 p = Pp[idx], q = Qp[idx];
        float v0 = fmaxf(p.x + q.x, 0.f);
        float v1 = fmaxf(p.y + q.y, 0.f);
        float v2 = fmaxf(p.z + q.z, 0.f);
        float v3 = fmaxf(p.w + q.w, 0.f);
        red_add_v4(Sp + idx*4, v0, v1, v2, v3);
    }
}

// ---------------- bf16x3 split mma.sync GEMM: [M,256] @ [256,256] ----------------
// CTA tile 128x256, BK=32, 256 threads, 8 warps (2 M x 4 N), warp tile 64x64.
// A = Ain node rows (cp.async). EPI:
//   2 = acc+bias -> BN(layer) -> relu -> += d_h -> d_h
//   3 = acc -> outp (raw)
//   4 = acc+bias -> outp
//   5 = relu(Ain2[row] + invdeg[row]*acc + bias + b2f[row]*cvec) -> outp
#define AROWSTR  40
#define BROWSTR  40
#define A_BYTES  (128*AROWSTR*4)
#define BH_BYTES (256*BROWSTR*2)
#define STAGE_BYTES (A_BYTES + 2*BH_BYTES)
#define SMEM_DYN (2*STAGE_BYTES)

template<int EPI>
__global__ __launch_bounds__(256, 1)
void tc_gemm(const unsigned short* __restrict__ WH, const unsigned short* __restrict__ WL,
             int ldB,
             const float* __restrict__ bias,
             float* __restrict__ outp,
             const float* __restrict__ Ain,
             const float* __restrict__ Ain2,     // EPI5: raw t2 read
             const float* __restrict__ cvec,     // EPI5: msg_b2@U1bot
             int K, int layer)
{
    extern __shared__ char dynsmem[];
    const uint32_t smem_base = smem_u32(dynsmem);

    const int tid  = threadIdx.x;
    const int lane = tid & 31;
    const int wid  = tid >> 5;
    const int wm   = wid & 1;
    const int wn   = wid >> 1;
    const int g    = lane >> 2;
    const int t4   = lane & 3;
    const int row0 = blockIdx.x * 128;

    const int rt = tid >> 3;
    const int cc = tid & 7;
    uint32_t sAoff[4], sBoff[8];
#pragma unroll
    for (int j = 0; j < 4; j++)
        sAoff[j] = (uint32_t)(rt + j*32)*(AROWSTR*4u) + (uint32_t)cc*16u;
#pragma unroll
    for (int j = 0; j < 8; j++)
        sBoff[j] = (uint32_t)(rt + j*32)*(BROWSTR*2u) + (uint32_t)(cc & 3)*16u;

    uint32_t aofs[4];
#pragma unroll
    for (int j = 0; j < 4; j++)
        aofs[j] = (uint32_t)(row0 + rt + j*32)*HID + cc*4u;

    const unsigned short* gB = ((cc < 4) ? WH : WL) + (size_t)rt*ldB + (cc & 3)*8;
    const uint32_t sBsel = (cc < 4) ? 0u : BH_BYTES;

    float acc[4][8][4];
#pragma unroll
    for (int mi = 0; mi < 4; mi++)
#pragma unroll
        for (int ni = 0; ni < 8; ni++)
#pragma unroll
            for (int r = 0; r < 4; r++) acc[mi][ni][r] = 0.f;

    const int NC = K >> 5;

    auto load_chunk = [&](int t, int stage) {
        const int k0 = t*32;
        uint32_t sa  = smem_base + (uint32_t)stage*STAGE_BYTES;
        uint32_t sbh = sa + A_BYTES + sBsel;
#pragma unroll
        for (int j = 0; j < 4; j++)
            cp_async16(sa + sAoff[j], Ain + aofs[j] + k0);
#pragma unroll
        for (int j = 0; j < 8; j++)
            cp_async16(sbh + sBoff[j], gB + (size_t)j*32*ldB + k0);
    };

    load_chunk(0, 0);
    CP_COMMIT();

    for (int t = 0; t < NC; t++) {
        if (t + 1 < NC) { load_chunk(t + 1, (t + 1) & 1); CP_COMMIT(); CP_WAIT1(); }
        else            { CP_WAIT0(); }
        __syncthreads();

        const char*  stg = dynsmem + (t & 1)*STAGE_BYTES;
        const float* sA  = (const float*)stg;
        const char*  sBH = stg + A_BYTES;
        const char*  sBL = sBH + BH_BYTES;
#pragma unroll
        for (int ks = 0; ks < 2; ks++) {
            const int kf = ks*16 + t4*2;
            uint32_t ahi[4][4], alo[4][4];
#pragma unroll
            for (int mi = 0; mi < 4; mi++) {
                const float* ap = sA + (wm*64 + mi*16 + g)*AROWSTR + kf;
                float2 v00 = *(const float2*)ap;
                float2 v10 = *(const float2*)(ap + 8*AROWSTR);
                float2 v01 = *(const float2*)(ap + 8);
                float2 v11 = *(const float2*)(ap + 8*AROWSTR + 8);
                split_bf16x2(v00, ahi[mi][0], alo[mi][0]);
                split_bf16x2(v10, ahi[mi][1], alo[mi][1]);
                split_bf16x2(v01, ahi[mi][2], alo[mi][2]);
                split_bf16x2(v11, ahi[mi][3], alo[mi][3]);
            }
#pragma unroll
            for (int ni = 0; ni < 8; ni++) {
                const uint32_t boff = (uint32_t)(wn*64 + ni*8 + g)*(BROWSTR*2u)
                                    + (uint32_t)(ks*16 + t4*2)*2u;
                uint32_t bhi[2] = { *(const uint32_t*)(sBH + boff),
                                    *(const uint32_t*)(sBH + boff + 16) };
                uint32_t blo[2] = { *(const uint32_t*)(sBL + boff),
                                    *(const uint32_t*)(sBL + boff + 16) };
#pragma unroll
                for (int mi = 0; mi < 4; mi++) {
                    mma_bf16(acc[mi][ni], ahi[mi], bhi);
                    mma_bf16(acc[mi][ni], ahi[mi], blo);
                    mma_bf16(acc[mi][ni], alo[mi], bhi);
                }
            }
        }
        __syncthreads();
    }

    // ---- epilogue (acc rows g + rh*8, cols t4*2 + ni*8) ----
    const int colb = wn*64 + t4*2;
    float2 bias2[8];
    if constexpr (EPI != 3) {
#pragma unroll
        for (int ni = 0; ni < 8; ni++)
            bias2[ni] = *(const float2*)(bias + colb + ni*8);
    }
    float2 sc2[8], sh2[8];
    if constexpr (EPI == 2) {
#pragma unroll
        for (int ni = 0; ni < 8; ni++) {
            sc2[ni] = *(const float2*)(d_bnscale + layer*HID + colb + ni*8);
            sh2[ni] = *(const float2*)(d_bnshift + layer*HID + colb + ni*8);
        }
    }
    float2 cv2[8];
    if constexpr (EPI == 5) {
#pragma unroll
        for (int ni = 0; ni < 8; ni++)
            cv2[ni] = *(const float2*)(cvec + colb + ni*8);
    }

#pragma unroll
    for (int mi = 0; mi < 4; mi++) {
#pragma unroll
        for (int rh = 0; rh < 2; rh++) {
            const int row = row0 + wm*64 + mi*16 + g + rh*8;
            if constexpr (EPI == 3) {
                float* op = outp + (size_t)row*HID + colb;
#pragma unroll
                for (int ni = 0; ni < 8; ni++)
                    *(float2*)(op + ni*8) = make_float2(acc[mi][ni][rh*2+0],
                                                        acc[mi][ni][rh*2+1]);
            } else if constexpr (EPI == 4) {
                float* op = outp + (size_t)row*HID + colb;
#pragma unroll
                for (int ni = 0; ni < 8; ni++)
                    *(float2*)(op + ni*8) = make_float2(acc[mi][ni][rh*2+0] + bias2[ni].x,
                                                        acc[mi][ni][rh*2+1] + bias2[ni].y);
            } else if constexpr (EPI == 5) {
                const float iv = __ldg(d_invdeg + row);
                const float bf = __ldg(d_b2f + row);
                const float* tp = Ain2 + (size_t)row*HID + colb;
                float* op = outp + (size_t)row*HID + colb;
#pragma unroll
                for (int ni = 0; ni < 8; ni++) {
                    float2 tv = *(const float2*)(tp + ni*8);
                    float u0 = tv.x + iv*acc[mi][ni][rh*2+0] + bias2[ni].x + bf*cv2[ni].x;
                    float u1 = tv.y + iv*acc[mi][ni][rh*2+1] + bias2[ni].y + bf*cv2[ni].y;
                    *(float2*)(op + ni*8) = make_float2(fmaxf(u0, 0.f), fmaxf(u1, 0.f));
                }
            } else { // EPI == 2
                float* hp = d_h + (size_t)row*HID + colb;
#pragma unroll
                for (int ni = 0; ni < 8; ni++) {
                    float2 res = *(float2*)(hp + ni*8);
                    float u0 = fmaf(acc[mi][ni][rh*2+0] + bias2[ni].x, sc2[ni].x, sh2[ni].x);
                    float u1 = fmaf(acc[mi][ni][rh*2+1] + bias2[ni].y, sc2[ni].y, sh2[ni].y);
                    *(float2*)(hp + ni*8) = make_float2(fmaxf(u0,0.f) + res.x,
                                                        fmaxf(u1,0.f) + res.y);
                }
            }
        }
    }
}

// out[row] = relu(R[u]+S[v]) . w2 + b2   (R has mlp_b1 folded in)
__global__ void final_pair_dot_kernel(const float* __restrict__ w2,
                                      const float* __restrict__ b2,
                                      float* __restrict__ out) {
    int row  = blockIdx.x*8 + (threadIdx.x >> 5);
    int lane = threadIdx.x & 31;
    int gg = row / 80, bb = row % 80;
    const float* R = d_P + (size_t)(gg*NPG + (bb % 57))*HID;
    const float* S = d_Q + (size_t)(gg*NPG + ((bb*13 + 1) % 57))*HID;
    float s = 0.f;
#pragma unroll
    for (int k = lane; k < HID; k += 32) {
        float v = fmaxf(R[k] + S[k], 0.f);
        s = fmaf(v, __ldg(w2 + k), s);
    }
#pragma unroll
    for (int o = 16; o > 0; o >>= 1) s += __shfl_down_sync(0xffffffffu, s, o);
    if (lane == 0) out[row] = s + b2[0];
}

// ---------------- launch ----------------
extern "C" void kernel_launch(void* const* d_in, const int* in_sizes, int n_in,
                              void* d_out, int out_size)
{
    const float* x      = (const float*)d_in[0];
    const int*   ei     = (const int*)  d_in[1];
    const float* in_w   = (const float*)d_in[3];
    const float* in_b   = (const float*)d_in[4];
    const float* msg_w1 = (const float*)d_in[5];
    const float* msg_b1 = (const float*)d_in[6];
    const float* msg_w2 = (const float*)d_in[7];
    const float* msg_b2 = (const float*)d_in[8];
    const float* upd_w1 = (const float*)d_in[9];
    const float* upd_b1 = (const float*)d_in[10];
    const float* upd_w2 = (const float*)d_in[11];
    const float* upd_b2 = (const float*)d_in[12];
    const float* bn_g   = (const float*)d_in[13];
    const float* bn_b   = (const float*)d_in[14];
    const float* bn_m   = (const float*)d_in[15];
    const float* bn_v   = (const float*)d_in[16];
    const float* mlp_w1 = (const float*)d_in[17];
    const float* mlp_b1 = (const float*)d_in[18];
    const float* mlp_w2 = (const float*)d_in[19];
    const float* mlp_b2 = (const float*)d_in[20];
    float* out = (float*)d_out;

    const int* srcI = ei;
    const int* dstI = ei + NEDGES;

    cudaFuncSetAttribute(tc_gemm<2>, cudaFuncAttributeMaxDynamicSharedMemorySize, SMEM_DYN);
    cudaFuncSetAttribute(tc_gemm<3>, cudaFuncAttributeMaxDynamicSharedMemorySize, SMEM_DYN);
    cudaFuncSetAttribute(tc_gemm<4>, cudaFuncAttributeMaxDynamicSharedMemorySize, SMEM_DYN);
    cudaFuncSetAttribute(tc_gemm<5>, cudaFuncAttributeMaxDynamicSharedMemorySize, SMEM_DYN);

    float *pP, *pQ, *pH, *pT2, *pAgg, *pWcf, *pCv;
    cudaGetSymbolAddress((void**)&pP,   d_P);
    cudaGetSymbolAddress((void**)&pQ,   d_Q);
    cudaGetSymbolAddress((void**)&pH,   d_h);
    cudaGetSymbolAddress((void**)&pT2,  d_t2);
    cudaGetSymbolAddress((void**)&pAgg, d_agg);
    cudaGetSymbolAddress((void**)&pWcf, d_wcf);
    cudaGetSymbolAddress((void**)&pCv,  d_cvec);
    unsigned short *pHm1,*pLm1,*pHu1,*pLu1,*pHu2,*pLu2,*pHc,*pLc,*pHr,*pLr;
    cudaGetSymbolAddress((void**)&pHm1, d_bhi_m1); cudaGetSymbolAddress((void**)&pLm1, d_blo_m1);
    cudaGetSymbolAddress((void**)&pHu1, d_bhi_u1); cudaGetSymbolAddress((void**)&pLu1, d_blo_u1);
    cudaGetSymbolAddress((void**)&pHu2, d_bhi_u2); cudaGetSymbolAddress((void**)&pLu2, d_blo_u2);
    cudaGetSymbolAddress((void**)&pHc,  d_bhi_c ); cudaGetSymbolAddress((void**)&pLc,  d_blo_c );
    cudaGetSymbolAddress((void**)&pHr,  d_bhi_r ); cudaGetSymbolAddress((void**)&pLr,  d_blo_r );

    // prep
    deg_zero_kernel <<<(NNODES+255)/256, 256>>>();
    deg_count_kernel<<<(NEDGES+255)/256, 256>>>(dstI);
    deg_inv_kernel  <<<(NNODES+255)/256, 256>>>();
    bn_prep_kernel  <<<(NLAY*HID+255)/256, 256>>>(bn_g, bn_b, bn_m, bn_v);
    input_gemm_kernel<<<NNODES, 256>>>(x, in_w, in_b);

    dim3 tb(32, 8);
    for (int l = 0; l < NLAY; l++) {
        transpose_split_kernel<0><<<dim3(16, 8), tb>>>(msg_w1 + (size_t)l*512*HID, l, 512);
        transpose_split_kernel<2><<<dim3(16, 8), tb>>>(upd_w1 + (size_t)l*512*HID, l, 512);
        transpose_split_kernel<3><<<dim3(8,  8), tb>>>(upd_w2 + (size_t)l*HID*HID, l, 256);
    }
    transpose_split_kernel<4><<<dim3(16, 8), tb>>>(mlp_w1, 0, 512);

    // precompute C_l = msg_w2 @ U1bot  (256x256), its split, and cvec_l = msg_b2 @ U1bot
    for (int l = 0; l < NLAY; l++) {
        const size_t o1 = (size_t)l*256*512;
        tc_gemm<3><<<2, 256, SMEM_DYN>>>(pHu1 + o1 + 256, pLu1 + o1 + 256, 512,
            nullptr, pWcf, msg_w2 + (size_t)l*HID*HID, nullptr, nullptr, 256, l);
        transpose_split_kernel<5><<<dim3(8, 8), tb>>>(pWcf, l, 256);
        cvec_kernel<<<1, 256>>>(msg_b2 + l*HID, upd_w1 + (size_t)l*512*HID, pCv + l*HID);
    }

    const int NGRID = NNODES/128;   // 912

    for (int l = 0; l < NLAY; l++) {
        const size_t o1 = (size_t)l*256*512;
        const size_t o2 = (size_t)l*256*256;
        zero_agg_kernel<<<2048, 256>>>();
        // P = h @ W1top + b1   |   Q = h @ W1bot
        tc_gemm<4><<<NGRID, 256, SMEM_DYN>>>(pHm1 + o1, pLm1 + o1, 512,
            msg_b1 + l*HID, pP, pH, nullptr, nullptr, 256, l);
        tc_gemm<3><<<NGRID, 256, SMEM_DYN>>>(pHm1 + o1 + 256, pLm1 + o1 + 256, 512,
            nullptr, pQ, pH, nullptr, nullptr, 256, l);
        // S[dst] += relu(P[dst] + Q[src])   (no edge GEMM!)
        edge_scatter_kernel<<<NEDGES/8, 256>>>(srcI, dstI);
        // t2 = h @ U1top (raw)
        tc_gemm<3><<<NGRID, 256, SMEM_DYN>>>(pHu1 + o1, pLu1 + o1, 512,
            nullptr, pT2, pH, nullptr, nullptr, 256, l);
        // t2 = relu(t2 + invdeg * (S @ C_l) + upd_b1 + b2f * cvec)
        tc_gemm<5><<<NGRID, 256, SMEM_DYN>>>(pHc + o2, pLc + o2, 256,
            upd_b1 + l*HID, pT2, pAgg, pT2, pCv + l*HID, 256, l);
        // h = relu(BN(t2 @ U2 + b2u)) + h
        tc_gemm<2><<<NGRID, 256, SMEM_DYN>>>(pHu2 + o2, pLu2 + o2, 256,
            upd_b2 + l*HID, nullptr, pT2, nullptr, nullptr, 256, l);
    }

    // readout: R = h@mlpW1top + b1 ; S = h@mlpW1bot ; out = relu(R[u]+S[v]).w2 + b2
    tc_gemm<4><<<NGRID, 256, SMEM_DYN>>>(pHr, pLr, 512,
        mlp_b1, pP, pH, nullptr, nullptr, 256, 0);
    tc_gemm<3><<<NGRID, 256, SMEM_DYN>>>(pHr + 256, pLr + 256, 512,
        nullptr, pQ, pH, nullptr, nullptr, 256, 0);
    final_pair_dot_kernel<<<NEF/8, 256>>>(mlp_w2, mlp_b2, out);
}